// round 11
// baseline (speedup 1.0000x reference)
#include <cuda_runtime.h>
#include <cfloat>

// VectorQuantization: N=32768 points, K=8192 codewords, D=256 (fp32 in)
// out[i] = argmin_k (||x_i||^2 + ||c_k||^2 - 2 x_i . c_k)
//
// R11: output written as FLOAT32 values (harness compares in fp32; int32
// bit patterns read as denormals ~= 0 explained the persistent rel_err=1.0).
// Core: verified double-buffered 64x128 tile, scalar FFMA 4x8 micro-tile.

#define N_PTS 32768
#define K_CB  8192
#define D_DIM 256

#define BM 64      // rows (points) per block
#define BN 128     // codewords per K-tile
#define DK 16      // depth chunk
#define XS_STRIDE 68   // 64 + 4 pad
#define CS_STRIDE 132  // 128 + 4 pad

__device__ __align__(16) float g_c2[K_CB];   // ||c_k||^2

// ---------------------------------------------------------------------------
// Kernel 1: codeword squared norms
// ---------------------------------------------------------------------------
__global__ void c2_kernel(const float* __restrict__ vecs) {
    int k = blockIdx.x * blockDim.x + threadIdx.x;
    if (k >= K_CB) return;
    const float* p = vecs + (size_t)k * D_DIM;
    float s = 0.f;
#pragma unroll 8
    for (int i = 0; i < D_DIM; ++i) s = fmaf(p[i], p[i], s);
    g_c2[k] = s;
}

// ---------------------------------------------------------------------------
// Kernel 2: fused GEMM + argmin
//   block = 256 threads (tx in [0,16), ty in [0,16))
//   thread micro-tile: 4 rows (ty*4..+3) x 8 cols (tx*4..+3, 64+tx*4..+3)
// ---------------------------------------------------------------------------
union SmemU {
    struct {
        float xs[2][DK][XS_STRIDE];   // x chunk, depth-major [depth][row]
        float cs[2][DK][CS_STRIDE];   // codeword chunk, depth-major [depth][col]
    } g;
    struct {
        float sc[BM][17];
        int   si[BM][17];
    } r;
};

__global__ __launch_bounds__(256)
void vq_kernel(const float* __restrict__ x, const float* __restrict__ vecs,
               float* __restrict__ out) {
    __shared__ SmemU sm;
    __shared__ float x2p[BM][4];   // partial row norms
    __shared__ float x2s[BM];      // ||x_row||^2

    const int tid = threadIdx.x;
    const int tx = tid & 15;
    const int ty = tid >> 4;
    const int rowBase = blockIdx.x * BM;

    // ---- row norms ||x||^2: row = tid>>2 handles quarter q = tid&3 ----
    {
        int row = tid >> 2, q = tid & 3;
        const float4* p = (const float4*)(x + (size_t)(rowBase + row) * D_DIM + q * 64);
        float part = 0.f;
#pragma unroll
        for (int i = 0; i < 16; ++i) {
            float4 v = p[i];
            part = fmaf(v.x, v.x, part);
            part = fmaf(v.y, v.y, part);
            part = fmaf(v.z, v.z, part);
            part = fmaf(v.w, v.w, part);
        }
        x2p[row][q] = part;
    }
    __syncthreads();
    if (tid < BM)
        x2s[tid] = ((x2p[tid][0] + x2p[tid][1]) + (x2p[tid][2] + x2p[tid][3]));
    // x2s consumed only in the ch==15 epilogue, which is preceded by the
    // __syncthreads() at the top of the pipeline below.

    float rbest[4];
    int   ridx[4];
#pragma unroll
    for (int i = 0; i < 4; ++i) { rbest[i] = FLT_MAX; ridx[i] = 0; }

    float acc[4][8];   // [row i][col j]; j<4 -> tx*4+j, j>=4 -> 64+tx*4+(j-4)

    const int xrow = tid >> 2;          // [0,64)
    const int xq   = tid & 3;           // float4 slot within 16-float chunk

    // ---- prologue: fill buffer 0 with chunk (kt=0, d0=0) ----
    {
        float4 vx = *(const float4*)(x + (size_t)(rowBase + xrow) * D_DIM + xq * 4);
        sm.g.xs[0][xq * 4 + 0][xrow] = vx.x;
        sm.g.xs[0][xq * 4 + 1][xrow] = vx.y;
        sm.g.xs[0][xq * 4 + 2][xrow] = vx.z;
        sm.g.xs[0][xq * 4 + 3][xrow] = vx.w;
#pragma unroll
        for (int s = 0; s < 2; ++s) {
            int idx = tid + 256 * s;
            int cr = idx >> 2, cq = idx & 3;
            float4 vc = *(const float4*)(vecs + (size_t)cr * D_DIM + cq * 4);
            sm.g.cs[0][cq * 4 + 0][cr] = vc.x;
            sm.g.cs[0][cq * 4 + 1][cr] = vc.y;
            sm.g.cs[0][cq * 4 + 2][cr] = vc.z;
            sm.g.cs[0][cq * 4 + 3][cr] = vc.w;
        }
    }
    __syncthreads();

    int buf = 0;
    const int NKT = K_CB / BN;           // 64
    const int TOT = NKT * (D_DIM / DK);  // 1024

    for (int it = 0; it < TOT; ++it) {
        const int kt = it >> 4;
        const int ch = it & 15;

        // ---- prefetch next chunk (global -> registers) ----
        float4 nrx, nrc0, nrc1;
        const bool hasNext = (it + 1) < TOT;
        if (hasNext) {
            const int nit = it + 1;
            const int nkt = nit >> 4;
            const int nd0 = (nit & 15) * DK;
            nrx = *(const float4*)(x + (size_t)(rowBase + xrow) * D_DIM + nd0 + xq * 4);
            int idx = tid;
            int cr = idx >> 2, cq = idx & 3;
            nrc0 = *(const float4*)(vecs + (size_t)(nkt * BN + cr) * D_DIM + nd0 + cq * 4);
            idx = tid + 256;
            cr = idx >> 2; cq = idx & 3;
            nrc1 = *(const float4*)(vecs + (size_t)(nkt * BN + cr) * D_DIM + nd0 + cq * 4);
        }

        if (ch == 0) {
#pragma unroll
            for (int i = 0; i < 4; ++i)
#pragma unroll
                for (int j = 0; j < 8; ++j) acc[i][j] = 0.f;
        }

        // ---- compute on current buffer: 16 depths x (4 rows x 8 cols) ----
#pragma unroll
        for (int kc = 0; kc < DK; ++kc) {
            float4 a  = *(const float4*)&sm.g.xs[buf][kc][ty * 4];
            float4 b0 = *(const float4*)&sm.g.cs[buf][kc][tx * 4];
            float4 b1 = *(const float4*)&sm.g.cs[buf][kc][64 + tx * 4];
            float av[4] = {a.x, a.y, a.z, a.w};
            float bv[8] = {b0.x, b0.y, b0.z, b0.w, b1.x, b1.y, b1.z, b1.w};
#pragma unroll
            for (int i = 0; i < 4; ++i)
#pragma unroll
                for (int j = 0; j < 8; ++j)
                    acc[i][j] = fmaf(av[i], bv[j], acc[i][j]);
        }

        // ---- store prefetched chunk into the other buffer ----
        if (hasNext) {
            const int nb = buf ^ 1;
            sm.g.xs[nb][xq * 4 + 0][xrow] = nrx.x;
            sm.g.xs[nb][xq * 4 + 1][xrow] = nrx.y;
            sm.g.xs[nb][xq * 4 + 2][xrow] = nrx.z;
            sm.g.xs[nb][xq * 4 + 3][xrow] = nrx.w;
            int idx = tid;
            int cr = idx >> 2, cq = idx & 3;
            sm.g.cs[nb][cq * 4 + 0][cr] = nrc0.x;
            sm.g.cs[nb][cq * 4 + 1][cr] = nrc0.y;
            sm.g.cs[nb][cq * 4 + 2][cr] = nrc0.z;
            sm.g.cs[nb][cq * 4 + 3][cr] = nrc0.w;
            idx = tid + 256;
            cr = idx >> 2; cq = idx & 3;
            sm.g.cs[nb][cq * 4 + 0][cr] = nrc1.x;
            sm.g.cs[nb][cq * 4 + 1][cr] = nrc1.y;
            sm.g.cs[nb][cq * 4 + 2][cr] = nrc1.z;
            sm.g.cs[nb][cq * 4 + 3][cr] = nrc1.w;
        }

        // ---- end-of-tile epilogue: fold tile scores into running argmin ----
        if (ch == 15) {
            const int colBase = kt * BN;
            float x2v[4];
#pragma unroll
            for (int i = 0; i < 4; ++i) x2v[i] = x2s[ty * 4 + i];
#pragma unroll
            for (int i = 0; i < 4; ++i) {
#pragma unroll
                for (int j = 0; j < 8; ++j) {
                    int col = colBase + (j >> 2) * 64 + tx * 4 + (j & 3);
                    float t = __fadd_rn(x2v[i], g_c2[col]);
                    float s = __fadd_rn(t, -2.0f * acc[i][j]);
                    if (s < rbest[i] || (s == rbest[i] && col < ridx[i])) {
                        rbest[i] = s; ridx[i] = col;
                    }
                }
            }
        }

        __syncthreads();
        buf ^= 1;
    }

    // ---- cross-thread (same-row) reduction via SMEM reuse ----
#pragma unroll
    for (int i = 0; i < 4; ++i) {
        int r = ty * 4 + i;
        sm.r.sc[r][tx] = rbest[i];
        sm.r.si[r][tx] = ridx[i];
    }
    __syncthreads();

    if (tid < BM) {
        float b = sm.r.sc[tid][0];
        int bi = sm.r.si[tid][0];
#pragma unroll
        for (int j = 1; j < 16; ++j) {
            float v = sm.r.sc[tid][j];
            int vi = sm.r.si[tid][j];
            if (v < b || (v == b && vi < bi)) { b = v; bi = vi; }
        }
        // KEY CHANGE: harness compares output as float32 -> write float VALUES
        out[rowBase + tid] = (float)bi;
    }
}

// ---------------------------------------------------------------------------
extern "C" void kernel_launch(void* const* d_in, const int* in_sizes, int n_in,
                              void* d_out, int out_size) {
    const float* p0 = (const float*)d_in[0];
    const float* p1 = (const float*)d_in[1];
    // x = N*D = 8388608 elems, vecs = K*D = 2097152 elems
    const float* x    = p0;
    const float* vecs = p1;
    if (n_in >= 2 && in_sizes[0] == K_CB * D_DIM && in_sizes[1] == N_PTS * D_DIM) {
        x = p1; vecs = p0;
    }
    float* out = (float*)d_out;

    c2_kernel<<<K_CB / 256, 256>>>(vecs);
    vq_kernel<<<N_PTS / BM, 256>>>(x, vecs, out);
}

// round 16
// speedup vs baseline: 1.0239x; 1.0239x over previous
#include <cuda_runtime.h>
#include <cfloat>

// VectorQuantization: N=32768 points, K=8192 codewords, D=256 (fp32 in)
// out[i] = (float) argmin_k (||x_i||^2 + ||c_k||^2 - 2 x_i . c_k)
//
// R13 = resubmit of R12 (infra failure): packed fma.rn.f32x2 core
// (2 MACs/instr) on the verified double-buffered 64x128 tile structure,
// float32 output values (the R11 fix).

#define N_PTS 32768
#define K_CB  8192
#define D_DIM 256

#define BM 64      // rows (points) per block
#define BN 128     // codewords per K-tile
#define DK 16      // depth chunk
#define XS_STRIDE 68   // 64 + 4 pad
#define CS_STRIDE 132  // 128 + 4 pad

__device__ __align__(16) float g_c2[K_CB];   // ||c_k||^2

typedef unsigned long long u64;

__device__ __forceinline__ u64 splat2(float a) {
    u64 r;
    asm("mov.b64 %0, {%1, %1};" : "=l"(r) : "f"(a));
    return r;
}
__device__ __forceinline__ void fma2(u64& d, u64 a, u64 b) {
    asm("fma.rn.f32x2 %0, %1, %2, %0;" : "+l"(d) : "l"(a), "l"(b));
}
__device__ __forceinline__ void unpack2(u64 v, float& lo, float& hi) {
    asm("mov.b64 {%0, %1}, %2;" : "=f"(lo), "=f"(hi) : "l"(v));
}

// ---------------------------------------------------------------------------
// Kernel 1: codeword squared norms
// ---------------------------------------------------------------------------
__global__ void c2_kernel(const float* __restrict__ vecs) {
    int k = blockIdx.x * blockDim.x + threadIdx.x;
    if (k >= K_CB) return;
    const float* p = vecs + (size_t)k * D_DIM;
    float s = 0.f;
#pragma unroll 8
    for (int i = 0; i < D_DIM; ++i) s = fmaf(p[i], p[i], s);
    g_c2[k] = s;
}

// ---------------------------------------------------------------------------
// Kernel 2: fused GEMM + argmin (f32x2 core)
//   block = 256 threads (tx in [0,16), ty in [0,16))
//   thread micro-tile: 4 rows (ty*4..+3) x 8 cols as 4 f32x2 pairs:
//   pair p -> cols (p>>1)*64 + tx*4 + (p&1)*2 + {0,1}
// ---------------------------------------------------------------------------
union SmemU {
    struct {
        float xs[2][DK][XS_STRIDE];   // x chunk, depth-major [depth][row]
        float cs[2][DK][CS_STRIDE];   // codeword chunk, depth-major [depth][col]
    } g;
    struct {
        float sc[BM][17];
        int   si[BM][17];
    } r;
};

__global__ __launch_bounds__(256)
void vq_kernel(const float* __restrict__ x, const float* __restrict__ vecs,
               float* __restrict__ out) {
    __shared__ SmemU sm;
    __shared__ float x2p[BM][4];
    __shared__ float x2s[BM];      // ||x_row||^2

    const int tid = threadIdx.x;
    const int tx = tid & 15;
    const int ty = tid >> 4;
    const int rowBase = blockIdx.x * BM;

    // ---- row norms ||x||^2 ----
    {
        int row = tid >> 2, q = tid & 3;
        const float4* p = (const float4*)(x + (size_t)(rowBase + row) * D_DIM + q * 64);
        float part = 0.f;
#pragma unroll
        for (int i = 0; i < 16; ++i) {
            float4 v = p[i];
            part = fmaf(v.x, v.x, part);
            part = fmaf(v.y, v.y, part);
            part = fmaf(v.z, v.z, part);
            part = fmaf(v.w, v.w, part);
        }
        x2p[row][q] = part;
    }
    __syncthreads();
    if (tid < BM)
        x2s[tid] = ((x2p[tid][0] + x2p[tid][1]) + (x2p[tid][2] + x2p[tid][3]));
    // consumed first in the ch==15 epilogue, ordered by the pipeline syncs

    float rbest[4];
    int   ridx[4];
#pragma unroll
    for (int i = 0; i < 4; ++i) { rbest[i] = FLT_MAX; ridx[i] = 0; }

    u64 acc[4][4];   // [row i][pair p]

    const int xrow = tid >> 2;
    const int xq   = tid & 3;

    // ---- prologue: fill buffer 0 with chunk (kt=0, d0=0) ----
    {
        float4 vx = *(const float4*)(x + (size_t)(rowBase + xrow) * D_DIM + xq * 4);
        sm.g.xs[0][xq * 4 + 0][xrow] = vx.x;
        sm.g.xs[0][xq * 4 + 1][xrow] = vx.y;
        sm.g.xs[0][xq * 4 + 2][xrow] = vx.z;
        sm.g.xs[0][xq * 4 + 3][xrow] = vx.w;
#pragma unroll
        for (int s = 0; s < 2; ++s) {
            int idx = tid + 256 * s;
            int cr = idx >> 2, cq = idx & 3;
            float4 vc = *(const float4*)(vecs + (size_t)cr * D_DIM + cq * 4);
            sm.g.cs[0][cq * 4 + 0][cr] = vc.x;
            sm.g.cs[0][cq * 4 + 1][cr] = vc.y;
            sm.g.cs[0][cq * 4 + 2][cr] = vc.z;
            sm.g.cs[0][cq * 4 + 3][cr] = vc.w;
        }
    }
    __syncthreads();

    int buf = 0;
    const int NKT = K_CB / BN;           // 64
    const int TOT = NKT * (D_DIM / DK);  // 1024

    for (int it = 0; it < TOT; ++it) {
        const int kt = it >> 4;
        const int ch = it & 15;

        // ---- prefetch next chunk (global -> registers) ----
        float4 nrx, nrc0, nrc1;
        const bool hasNext = (it + 1) < TOT;
        if (hasNext) {
            const int nit = it + 1;
            const int nkt = nit >> 4;
            const int nd0 = (nit & 15) * DK;
            nrx = *(const float4*)(x + (size_t)(rowBase + xrow) * D_DIM + nd0 + xq * 4);
            int idx = tid;
            int cr = idx >> 2, cq = idx & 3;
            nrc0 = *(const float4*)(vecs + (size_t)(nkt * BN + cr) * D_DIM + nd0 + cq * 4);
            idx = tid + 256;
            cr = idx >> 2; cq = idx & 3;
            nrc1 = *(const float4*)(vecs + (size_t)(nkt * BN + cr) * D_DIM + nd0 + cq * 4);
        }

        if (ch == 0) {
#pragma unroll
            for (int i = 0; i < 4; ++i)
#pragma unroll
                for (int p = 0; p < 4; ++p) acc[i][p] = 0ull;
        }

        // ---- compute: 16 depths x (4 rows x 4 f32x2 pairs) ----
#pragma unroll
        for (int kc = 0; kc < DK; ++kc) {
            float4 a = *(const float4*)&sm.g.xs[buf][kc][ty * 4];
            ulonglong2 bA = *(const ulonglong2*)&sm.g.cs[buf][kc][tx * 4];
            ulonglong2 bB = *(const ulonglong2*)&sm.g.cs[buf][kc][64 + tx * 4];
            u64 a0 = splat2(a.x), a1 = splat2(a.y), a2 = splat2(a.z), a3 = splat2(a.w);
            fma2(acc[0][0], a0, bA.x); fma2(acc[0][1], a0, bA.y);
            fma2(acc[0][2], a0, bB.x); fma2(acc[0][3], a0, bB.y);
            fma2(acc[1][0], a1, bA.x); fma2(acc[1][1], a1, bA.y);
            fma2(acc[1][2], a1, bB.x); fma2(acc[1][3], a1, bB.y);
            fma2(acc[2][0], a2, bA.x); fma2(acc[2][1], a2, bA.y);
            fma2(acc[2][2], a2, bB.x); fma2(acc[2][3], a2, bB.y);
            fma2(acc[3][0], a3, bA.x); fma2(acc[3][1], a3, bA.y);
            fma2(acc[3][2], a3, bB.x); fma2(acc[3][3], a3, bB.y);
        }

        // ---- store prefetched chunk into the other buffer ----
        if (hasNext) {
            const int nb = buf ^ 1;
            sm.g.xs[nb][xq * 4 + 0][xrow] = nrx.x;
            sm.g.xs[nb][xq * 4 + 1][xrow] = nrx.y;
            sm.g.xs[nb][xq * 4 + 2][xrow] = nrx.z;
            sm.g.xs[nb][xq * 4 + 3][xrow] = nrx.w;
            int idx = tid;
            int cr = idx >> 2, cq = idx & 3;
            sm.g.cs[nb][cq * 4 + 0][cr] = nrc0.x;
            sm.g.cs[nb][cq * 4 + 1][cr] = nrc0.y;
            sm.g.cs[nb][cq * 4 + 2][cr] = nrc0.z;
            sm.g.cs[nb][cq * 4 + 3][cr] = nrc0.w;
            idx = tid + 256;
            cr = idx >> 2; cq = idx & 3;
            sm.g.cs[nb][cq * 4 + 0][cr] = nrc1.x;
            sm.g.cs[nb][cq * 4 + 1][cr] = nrc1.y;
            sm.g.cs[nb][cq * 4 + 2][cr] = nrc1.z;
            sm.g.cs[nb][cq * 4 + 3][cr] = nrc1.w;
        }

        // ---- end-of-tile epilogue: fold tile scores into running argmin ----
        if (ch == 15) {
            const int colBase = kt * BN;
            float x2v[4];
#pragma unroll
            for (int i = 0; i < 4; ++i) x2v[i] = x2s[ty * 4 + i];
#pragma unroll
            for (int i = 0; i < 4; ++i) {
#pragma unroll
                for (int p = 0; p < 4; ++p) {
                    float lo, hi;
                    unpack2(acc[i][p], lo, hi);
                    int c0 = colBase + (p >> 1) * 64 + tx * 4 + (p & 1) * 2;
                    float t0 = __fadd_rn(x2v[i], g_c2[c0]);
                    float s0 = __fadd_rn(t0, -2.0f * lo);
                    float t1 = __fadd_rn(x2v[i], g_c2[c0 + 1]);
                    float s1 = __fadd_rn(t1, -2.0f * hi);
                    if (s0 < rbest[i] || (s0 == rbest[i] && c0 < ridx[i])) {
                        rbest[i] = s0; ridx[i] = c0;
                    }
                    if (s1 < rbest[i] || (s1 == rbest[i] && (c0 + 1) < ridx[i])) {
                        rbest[i] = s1; ridx[i] = c0 + 1;
                    }
                }
            }
        }

        __syncthreads();
        buf ^= 1;
    }

    // ---- cross-thread (same-row) reduction via SMEM reuse ----
#pragma unroll
    for (int i = 0; i < 4; ++i) {
        int r = ty * 4 + i;
        sm.r.sc[r][tx] = rbest[i];
        sm.r.si[r][tx] = ridx[i];
    }
    __syncthreads();

    if (tid < BM) {
        float b = sm.r.sc[tid][0];
        int bi = sm.r.si[tid][0];
#pragma unroll
        for (int j = 1; j < 16; ++j) {
            float v = sm.r.sc[tid][j];
            int vi = sm.r.si[tid][j];
            if (v < b || (v == b && vi < bi)) { b = v; bi = vi; }
        }
        out[rowBase + tid] = (float)bi;   // float32 output values
    }
}

// ---------------------------------------------------------------------------
extern "C" void kernel_launch(void* const* d_in, const int* in_sizes, int n_in,
                              void* d_out, int out_size) {
    const float* p0 = (const float*)d_in[0];
    const float* p1 = (const float*)d_in[1];
    const float* x    = p0;
    const float* vecs = p1;
    if (n_in >= 2 && in_sizes[0] == K_CB * D_DIM && in_sizes[1] == N_PTS * D_DIM) {
        x = p1; vecs = p0;
    }
    float* out = (float*)d_out;

    c2_kernel<<<K_CB / 256, 256>>>(vecs);
    vq_kernel<<<N_PTS / BM, 256>>>(x, vecs, out);
}